// round 12
// baseline (speedup 1.0000x reference)
#include <cuda_runtime.h>
#include <cuda_fp16.h>
#include <cstdint>

// out[b,t] = cumsum_t( relu(x @ Wh^T + bh) ) + (x @ Wb^T + bb)
//   x [16384,1024] f32, Wh [512,1024] f32, bh[512], Wb[1,1024], bb[1]
//
// fp16 mma.sync m16n8k16. CTA = 32 rows x 512 cols, 256 threads (8 warps,
// warp tile 32x64), 2 CTAs/SM. KCHUNK=32, 32 chunks.
// Wh pre-converted to fp16 FRAGMENT-ORDER in gmem (prepass); B fragments
// stream via coalesced LDG.128 with consume-then-reload.
// KEY FIX (R12): per chunk the 32 MMAs are issued in TWO PASSES of 16
// independent MMAs (all b.xy then all b.zw), growing the accumulator RAW
// distance from 2 to 16 instructions so 4 warps/SMSP saturate the pipe.
// A (x): LDG float4 prefetch -> fp16 convert -> STS into tiny 2-stage xs.
// In-register scan epilogue + fused fp32 base GEMV.

#define DDIM   1024
#define TDIM   512
#define BROWS  16384
#define MTILE  32
#define KCHUNK 32
#define NCH    32
#define NTHREADS 256

// static smem layout (bytes)
#define XS_O   0        // 2 x 2048 fp16 x, fragment order
#define WB_O   4096     // 1024 f32
#define BH_O   8192     // 512 f32
#define BASE_O 10240    // 32 f32
#define SEG_O  10368    // 256 f32
#define SMEM_SZ 11392

__device__ __half g_whs[TDIM * DDIM];  // [chunk c][col-group jg][lane][8 halfs]

__device__ __forceinline__ void mma_f16(float* c, uint32_t a0, uint32_t a1,
                                        uint32_t a2, uint32_t a3,
                                        uint32_t b0, uint32_t b1) {
    asm volatile(
        "mma.sync.aligned.m16n8k16.row.col.f32.f16.f16.f32 "
        "{%0,%1,%2,%3}, {%4,%5,%6,%7}, {%8,%9}, {%0,%1,%2,%3};"
        : "+f"(c[0]), "+f"(c[1]), "+f"(c[2]), "+f"(c[3])
        : "r"(a0), "r"(a1), "r"(a2), "r"(a3), "r"(b0), "r"(b1));
}

// prepass: Wh -> fp16 fragment-order:
//   (t,k): c=k>>5, G=(k>>4)&1, u=(k>>3)&1, lk=(k&7)>>1, w=k&1
//   jg=t>>3, l4=t&7, lane=4*l4+lk, h=4*G+2*u+w
__global__ void __launch_bounds__(256) prep_wh_kernel(const float* __restrict__ Wh) {
    const int t  = blockIdx.x;
    const int k4 = threadIdx.x * 4;
    float4 v = *(const float4*)(Wh + (size_t)t * DDIM + k4);
    const int jg = t >> 3, l4 = t & 7;
    #pragma unroll
    for (int e = 0; e < 4; e++) {
        int k = k4 + e;
        int c = k >> 5, G = (k >> 4) & 1, u = (k >> 3) & 1;
        int lk = (k & 7) >> 1, w = k & 1;
        g_whs[(size_t)c * 16384 + jg * 256 + (4 * l4 + lk) * 8 + 4 * G + 2 * u + w] =
            __float2half_rn(((const float*)&v)[e]);
    }
}

__global__ void __launch_bounds__(NTHREADS, 2)
surv_f16g_kernel(const float* __restrict__ x,
                 const float* __restrict__ bh,
                 const float* __restrict__ Wb,
                 const float* __restrict__ bb,
                 float* __restrict__ out)
{
    __shared__ __align__(16) char smc[SMEM_SZ];
    float* wb_s   = (float*)(smc + WB_O);
    float* bh_s   = (float*)(smc + BH_O);
    float* base_s = (float*)(smc + BASE_O);
    float* seg_s  = (float*)(smc + SEG_O);

    const int tid  = threadIdx.x;
    const int nw   = tid >> 5;         // warp = 64-col group (0..7)
    const int lane = tid & 31;
    const int l4   = lane >> 2;
    const int lk   = lane & 3;
    const int row0 = blockIdx.x * MTILE;

    // B direct-LDG base: chunk c -> + c*32768, slice j -> + j*512 (bytes)
    const char* bgm = (const char*)g_whs + nw * 4096 + lane * 16;

    // x convert addressing: row = tid>>3 (0..31), kq = tid&7 (float4 of k)
    const int row = tid >> 3;
    const int kq  = tid & 7;
    const float* xsrc = x + (size_t)(row0 + row) * DDIM + kq * 4;
    const int conv_off = ((row >> 4) * 2 + (kq >> 2)) * 512 +
                         (4 * (row & 7) + 2 * (kq & 1)) * 16 +
                         ((row >> 3) & 1) * 4 + ((kq >> 1) & 1) * 8;

    float acc[2][8][4];
    #pragma unroll
    for (int i = 0; i < 2; i++)
        #pragma unroll
        for (int j = 0; j < 8; j++)
            #pragma unroll
            for (int q = 0; q < 4; q++) acc[i][j][q] = 0.f;
    float bacc = 0.f;

    // preload Wb + bh
    #pragma unroll
    for (int i = 0; i < 4; i++) wb_s[tid + 256 * i] = Wb[tid + 256 * i];
    bh_s[tid]       = bh[tid];
    bh_s[tid + 256] = bh[tid + 256];

    // B fragments for chunk 0
    uint4 LB[8];
    #pragma unroll
    for (int j = 0; j < 8; j++)
        LB[j] = *(const uint4*)(bgm + j * 512);

    __syncthreads();   // wb_s visible

    // chunk0 convert + base; prefetch x chunk1
    float4 px = *(const float4*)(xsrc);
    {
        const float4 wv = *(const float4*)(wb_s + kq * 4);
        bacc = fmaf(px.x, wv.x, bacc); bacc = fmaf(px.y, wv.y, bacc);
        bacc = fmaf(px.z, wv.z, bacc); bacc = fmaf(px.w, wv.w, bacc);
        *(__half2*)(smc + XS_O + conv_off)      = __floats2half2_rn(px.x, px.y);
        *(__half2*)(smc + XS_O + conv_off + 16) = __floats2half2_rn(px.z, px.w);
    }
    px = *(const float4*)(xsrc + KCHUNK);

    #pragma unroll 1
    for (int c = 0; c < NCH; c++) {
        __syncthreads();   // xs(c) visible; xs((c+1)&1) free to overwrite

        if (c + 1 < NCH) {   // base fma + convert chunk c+1 from px regs
            const float4 wv = *(const float4*)(wb_s + (c + 1) * KCHUNK + kq * 4);
            bacc = fmaf(px.x, wv.x, bacc); bacc = fmaf(px.y, wv.y, bacc);
            bacc = fmaf(px.z, wv.z, bacc); bacc = fmaf(px.w, wv.w, bacc);
            char* xb = smc + XS_O + ((c + 1) & 1) * 2048 + conv_off;
            *(__half2*)(xb)      = __floats2half2_rn(px.x, px.y);
            *(__half2*)(xb + 16) = __floats2half2_rn(px.z, px.w);
        }
        if (c + 2 < NCH)
            px = *(const float4*)(xsrc + (c + 2) * KCHUNK);

        // ---- MMA chunk c: TWO PASSES of 16 independent MMAs ----
        const char* bsrc_next =
            bgm + (size_t)((c + 1 < NCH) ? (c + 1) : c) * 32768;

        const char* xaddr = smc + XS_O + (c & 1) * 2048 + lane * 16;
        uint4 LA00 = *(const uint4*)(xaddr);            // i0 G0
        uint4 LA01 = *(const uint4*)(xaddr + 512);      // i0 G1
        uint4 LA10 = *(const uint4*)(xaddr + 1024);     // i1 G0
        uint4 LA11 = *(const uint4*)(xaddr + 1536);     // i1 G1

        // pass 1: all b.xy (16 independent MMAs)
        #pragma unroll
        for (int j = 0; j < 8; j++) {
            mma_f16(acc[0][j], LA00.x, LA00.y, LA00.z, LA00.w, LB[j].x, LB[j].y);
            mma_f16(acc[1][j], LA10.x, LA10.y, LA10.z, LA10.w, LB[j].x, LB[j].y);
        }
        // pass 2: all b.zw (16 independent MMAs, RAW distance 16) + reload
        #pragma unroll
        for (int j = 0; j < 8; j++) {
            uint32_t bz = LB[j].z, bw = LB[j].w;
            LB[j] = *(const uint4*)(bsrc_next + j * 512);   // after last use
            mma_f16(acc[0][j], LA01.x, LA01.y, LA01.z, LA01.w, bz, bw);
            mma_f16(acc[1][j], LA11.x, LA11.y, LA11.z, LA11.w, bz, bw);
        }
    }

    // ---- base reduce: 8 lanes (kq) per row ----
    bacc += __shfl_down_sync(0xffffffffu, bacc, 4, 8);
    bacc += __shfl_down_sync(0xffffffffu, bacc, 2, 8);
    bacc += __shfl_down_sync(0xffffffffu, bacc, 1, 8);
    if (kq == 0) base_s[row] = bacc;

    // ---- per-row segmented scan over this warp's 64 cols ----
    float2 bhv[8];
    #pragma unroll
    for (int j = 0; j < 8; j++)
        bhv[j] = *(const float2*)(bh_s + nw * 64 + 8 * j + 2 * lk);

    #pragma unroll
    for (int i = 0; i < 2; i++) {
        #pragma unroll
        for (int hh = 0; hh < 2; hh++) {
            const int r = 16 * i + 8 * hh + l4;
            float carry = 0.f;
            #pragma unroll
            for (int j = 0; j < 8; j++) {
                float v0 = fmaxf(acc[i][j][2 * hh]     + bhv[j].x, 0.f);
                float v1 = fmaxf(acc[i][j][2 * hh + 1] + bhv[j].y, 0.f);
                float p = v0 + v1;
                float incl = p, t;
                t = __shfl_up_sync(0xffffffffu, incl, 1, 4); if (lk >= 1) incl += t;
                t = __shfl_up_sync(0xffffffffu, incl, 2, 4); if (lk >= 2) incl += t;
                float excl = incl - p;
                acc[i][j][2 * hh]     = carry + excl + v0;
                acc[i][j][2 * hh + 1] = carry + incl;
                carry += __shfl_sync(0xffffffffu, incl, 3, 4);
            }
            if (lk == 0) seg_s[r * 8 + nw] = carry;
        }
    }
    __syncthreads();

    // ---- cross-warp segment prefix + base, store ----
    const float bbv = bb[0];
    #pragma unroll
    for (int i = 0; i < 2; i++) {
        #pragma unroll
        for (int hh = 0; hh < 2; hh++) {
            const int r = 16 * i + 8 * hh + l4;
            float g = base_s[r] + bbv;
            #pragma unroll
            for (int s = 0; s < 8; s++)
                if (s < nw) g += seg_s[r * 8 + s];
            float* orow = out + (size_t)(row0 + r) * TDIM + nw * 64 + 2 * lk;
            #pragma unroll
            for (int j = 0; j < 8; j++) {
                float2 o;
                o.x = acc[i][j][2 * hh]     + g;
                o.y = acc[i][j][2 * hh + 1] + g;
                *(float2*)(orow + 8 * j) = o;
            }
        }
    }
}

extern "C" void kernel_launch(void* const* d_in, const int* in_sizes, int n_in,
                              void* d_out, int out_size)
{
    const float* x  = (const float*)d_in[0];
    const float* Wh = (const float*)d_in[1];
    const float* bh = (const float*)d_in[2];
    const float* Wb = (const float*)d_in[3];
    const float* bb = (const float*)d_in[4];
    float* out = (float*)d_out;
    (void)in_sizes; (void)n_in; (void)out_size;

    prep_wh_kernel<<<TDIM, 256>>>(Wh);
    surv_f16g_kernel<<<BROWS / MTILE, NTHREADS>>>(x, bh, Wb, bb, out);
}

// round 13
// speedup vs baseline: 1.2555x; 1.2555x over previous
#include <cuda_runtime.h>
#include <cuda_fp16.h>
#include <cstdint>

// out[b,t] = cumsum_t( relu(x @ Wh^T + bh) ) + (x @ Wb^T + bb)
//   x [16384,1024] f32, Wh [512,1024] f32, bh[512], Wb[1,1024], bb[1]
//
// fp16 mma.sync m16n8k16. CTA = 32 rows x 512 cols, 256 threads (8 warps,
// warp tile 32x64), 2 CTAs/SM, grid 512.
// R13: FULLY WARP-INDEPENDENT mainloop -- zero CTA barriers:
//  - A: g_xh fragment-order (prep_x) via WARP-PRIVATE cp.async 4-stage ring
//    (per-warp commit/wait_group; 3-chunk slack covers DRAM latency)
//  - B: g_whs fragment-order (prep_wh), direct LDG.128 consume-then-reload
//    (full-chunk slack; L1/L2 resident)
//  - base GEMV: deterministic per-chunk partials g_bp (prep_x), reduced in
//    fixed order in the epilogue (no atomics)
// One CTA barrier total (epilogue segment exchange).

#define DDIM   1024
#define TDIM   512
#define BROWS  16384
#define MTILE  32
#define NCH    32
#define NTHREADS 256

__device__ __half g_whs[TDIM * DDIM];     // B: [chunk][jg][lane][8 halfs]
__device__ __half g_xh[BROWS * DDIM];     // A: [tile][chunk][(i,G)][lane][8 halfs]
__device__ float  g_bp[(BROWS / MTILE) * MTILE * NCH];  // [tile][row32][chunk]

__device__ __forceinline__ void mma_f16(float* c, uint32_t a0, uint32_t a1,
                                        uint32_t a2, uint32_t a3,
                                        uint32_t b0, uint32_t b1) {
    asm volatile(
        "mma.sync.aligned.m16n8k16.row.col.f32.f16.f16.f32 "
        "{%0,%1,%2,%3}, {%4,%5,%6,%7}, {%8,%9}, {%0,%1,%2,%3};"
        : "+f"(c[0]), "+f"(c[1]), "+f"(c[2]), "+f"(c[3])
        : "r"(a0), "r"(a1), "r"(a2), "r"(a3), "r"(b0), "r"(b1));
}
__device__ __forceinline__ void cp16(void* dst_s, const void* src_g) {
    uint32_t d = (uint32_t)__cvta_generic_to_shared(dst_s);
    asm volatile("cp.async.cg.shared.global [%0], [%1], 16;" :: "r"(d), "l"(src_g));
}

// prepass B: Wh -> fp16 fragment order (proven R8-R12)
__global__ void __launch_bounds__(256) prep_wh_kernel(const float* __restrict__ Wh) {
    const int t  = blockIdx.x;
    const int k4 = threadIdx.x * 4;
    float4 v = *(const float4*)(Wh + (size_t)t * DDIM + k4);
    const int jg = t >> 3, l4 = t & 7;
    #pragma unroll
    for (int e = 0; e < 4; e++) {
        int k = k4 + e;
        int c = k >> 5, G = (k >> 4) & 1, u = (k >> 3) & 1;
        int lk = (k & 7) >> 1, w = k & 1;
        g_whs[(size_t)c * 16384 + jg * 256 + (4 * l4 + lk) * 8 + 4 * G + 2 * u + w] =
            __float2half_rn(((const float*)&v)[e]);
    }
}

// prepass A: block = (chunk, tile). 128 thr: thread (r = t>>2, q = t&3) owns
// 8 floats of row r. Produces: (a) fp16 fragment-order 2KB block of g_xh
// (smem-staged, coalesced uint4 stores); (b) deterministic base partial
// g_bp[tile*1024 + r*32 + chunk] = sum_k x[row][k]*Wb[k] over this chunk.
__global__ void __launch_bounds__(128) prep_x_kernel(const float* __restrict__ x,
                                                     const float* __restrict__ Wb) {
    const int chunk = blockIdx.x;
    const int tile  = blockIdx.y;
    const int t = threadIdx.x;
    const int r = t >> 2;          // 0..31
    const int q = t & 3;           // 8-float group
    const int gk = chunk * 32 + q * 8;
    const int grow = tile * 32 + r;

    float4 v0 = *(const float4*)(x + (size_t)grow * DDIM + gk);
    float4 v1 = *(const float4*)(x + (size_t)grow * DDIM + gk + 4);
    float4 w0 = *(const float4*)(Wb + gk);
    float4 w1 = *(const float4*)(Wb + gk + 4);

    float p = v0.x * w0.x + v0.y * w0.y + v0.z * w0.z + v0.w * w0.w
            + v1.x * w1.x + v1.y * w1.y + v1.z * w1.z + v1.w * w1.w;
    p += __shfl_down_sync(0xffffffffu, p, 2, 4);
    p += __shfl_down_sync(0xffffffffu, p, 1, 4);
    if (q == 0) g_bp[tile * 1024 + r * 32 + chunk] = p;

    __shared__ __half sbuf[2048];
    const int ii = (r >> 4) & 1, rh = (r >> 3) & 1, l4r = r & 7;
    #pragma unroll
    for (int e = 0; e < 8; e++) {
        int k5 = q * 8 + e;
        int G = (k5 >> 4) & 1, u = (k5 >> 3) & 1, lk = (k5 & 7) >> 1, w_ = k5 & 1;
        float f = (e < 4) ? ((const float*)&v0)[e] : ((const float*)&v1)[e - 4];
        sbuf[(ii * 2 + G) * 256 + (4 * l4r + lk) * 8 + 4 * u + 2 * rh + w_] =
            __float2half_rn(f);
    }
    __syncthreads();
    *(uint4*)((char*)g_xh + (size_t)(tile * 32 + chunk) * 2048 + t * 16) =
        *(const uint4*)((const char*)sbuf + t * 16);
}

__global__ void __launch_bounds__(NTHREADS, 2)
surv_f16h_kernel(const float* __restrict__ bh,
                 const float* __restrict__ bb,
                 float* __restrict__ out)
{
    __shared__ __align__(16) char As[8 * 4 * 2048];   // per-warp 4-stage A rings
    __shared__ float seg_s[MTILE * 8];
    __shared__ float base_s[MTILE];

    const int tid  = threadIdx.x;
    const int nw   = tid >> 5;
    const int lane = tid & 31;
    const int l4   = lane >> 2;
    const int lk   = lane & 3;
    const int tile = blockIdx.x;
    const int row0 = tile * MTILE;

    // A cp.async: this lane copies 4x16B per chunk into its warp's ring stage
    const char* axsrc = (const char*)g_xh + (size_t)tile * 65536 + lane * 16;
    char* aring = As + nw * 8192 + lane * 16;

    // B direct-LDG base
    const char* bgm = (const char*)g_whs + nw * 4096 + lane * 16;

    float acc[2][8][4];
    #pragma unroll
    for (int i = 0; i < 2; i++)
        #pragma unroll
        for (int j = 0; j < 8; j++)
            #pragma unroll
            for (int q = 0; q < 4; q++) acc[i][j][q] = 0.f;

    // prologue: A stages 0..2 (3 groups), B chunk 0
    #pragma unroll
    for (int s = 0; s < 3; s++) {
        const char* src = axsrc + (size_t)s * 2048;
        char* dst = aring + s * 2048;
        #pragma unroll
        for (int i = 0; i < 4; i++)
            cp16(dst + i * 512, src + i * 512);
        asm volatile("cp.async.commit_group;" ::: "memory");
    }
    uint4 LB[8];
    #pragma unroll
    for (int j = 0; j < 8; j++)
        LB[j] = *(const uint4*)(bgm + j * 512);

    // ---- mainloop: warp-independent, no CTA barriers ----
    #pragma unroll 1
    for (int c = 0; c < NCH; c++) {
        if (c <= NCH - 3)      asm volatile("cp.async.wait_group 2;" ::: "memory");
        else if (c == NCH - 2) asm volatile("cp.async.wait_group 1;" ::: "memory");
        else                   asm volatile("cp.async.wait_group 0;" ::: "memory");
        __syncwarp();

        const char* xaddr = aring - lane * 16 + (c & 3) * 2048 + lane * 16;
        uint4 LA00 = *(const uint4*)(xaddr);
        uint4 LA01 = *(const uint4*)(xaddr + 512);
        uint4 LA10 = *(const uint4*)(xaddr + 1024);
        uint4 LA11 = *(const uint4*)(xaddr + 1536);

        if (c + 3 < NCH) {   // refill ring stage (c+3)&3 (free since last iter)
            const char* src = axsrc + (size_t)(c + 3) * 2048;
            char* dst = aring + ((c + 3) & 3) * 2048;
            #pragma unroll
            for (int i = 0; i < 4; i++)
                cp16(dst + i * 512, src + i * 512);
            asm volatile("cp.async.commit_group;" ::: "memory");
        }

        const char* bnext = bgm + (size_t)((c + 1 < NCH) ? (c + 1) : c) * 32768;
        #pragma unroll
        for (int j = 0; j < 8; j++) {
            uint4 b = LB[j];
            mma_f16(acc[0][j], LA00.x, LA00.y, LA00.z, LA00.w, b.x, b.y);
            mma_f16(acc[1][j], LA10.x, LA10.y, LA10.z, LA10.w, b.x, b.y);
            mma_f16(acc[0][j], LA01.x, LA01.y, LA01.z, LA01.w, b.z, b.w);
            mma_f16(acc[1][j], LA11.x, LA11.y, LA11.z, LA11.w, b.z, b.w);
            LB[j] = *(const uint4*)(bnext + j * 512);   // ~full chunk of slack
        }
    }

    // ---- base: reduce per-chunk partials in fixed order ----
    {
        const int r  = tid >> 3;       // 0..31
        const int kq = tid & 7;
        const float* bp = g_bp + tile * 1024 + r * 32 + kq * 4;
        float4 p4 = *(const float4*)bp;
        float p = (p4.x + p4.y) + (p4.z + p4.w);
        p += __shfl_down_sync(0xffffffffu, p, 4, 8);
        p += __shfl_down_sync(0xffffffffu, p, 2, 8);
        p += __shfl_down_sync(0xffffffffu, p, 1, 8);
        if (kq == 0) base_s[r] = p;
    }

    // ---- per-row segmented scan over this warp's 64 cols ----
    float2 bhv[8];
    #pragma unroll
    for (int j = 0; j < 8; j++)
        bhv[j] = __ldg((const float2*)(bh + nw * 64 + 8 * j + 2 * lk));

    #pragma unroll
    for (int i = 0; i < 2; i++) {
        #pragma unroll
        for (int hh = 0; hh < 2; hh++) {
            const int r = 16 * i + 8 * hh + l4;
            float carry = 0.f;
            #pragma unroll
            for (int j = 0; j < 8; j++) {
                float v0 = fmaxf(acc[i][j][2 * hh]     + bhv[j].x, 0.f);
                float v1 = fmaxf(acc[i][j][2 * hh + 1] + bhv[j].y, 0.f);
                float p = v0 + v1;
                float incl = p, t;
                t = __shfl_up_sync(0xffffffffu, incl, 1, 4); if (lk >= 1) incl += t;
                t = __shfl_up_sync(0xffffffffu, incl, 2, 4); if (lk >= 2) incl += t;
                float excl = incl - p;
                acc[i][j][2 * hh]     = carry + excl + v0;
                acc[i][j][2 * hh + 1] = carry + incl;
                carry += __shfl_sync(0xffffffffu, incl, 3, 4);
            }
            if (lk == 0) seg_s[r * 8 + nw] = carry;
        }
    }
    __syncthreads();   // the ONE CTA barrier

    // ---- cross-warp segment prefix + base, store ----
    const float bbv = bb[0];
    #pragma unroll
    for (int i = 0; i < 2; i++) {
        #pragma unroll
        for (int hh = 0; hh < 2; hh++) {
            const int r = 16 * i + 8 * hh + l4;
            float g = base_s[r] + bbv;
            #pragma unroll
            for (int s = 0; s < 8; s++)
                if (s < nw) g += seg_s[r * 8 + s];
            float* orow = out + (size_t)(row0 + r) * TDIM + nw * 64 + 2 * lk;
            #pragma unroll
            for (int j = 0; j < 8; j++) {
                float2 o;
                o.x = acc[i][j][2 * hh]     + g;
                o.y = acc[i][j][2 * hh + 1] + g;
                *(float2*)(orow + 8 * j) = o;
            }
        }
    }
}

extern "C" void kernel_launch(void* const* d_in, const int* in_sizes, int n_in,
                              void* d_out, int out_size)
{
    const float* x  = (const float*)d_in[0];
    const float* Wh = (const float*)d_in[1];
    const float* bh = (const float*)d_in[2];
    const float* Wb = (const float*)d_in[3];
    const float* bb = (const float*)d_in[4];
    float* out = (float*)d_out;
    (void)in_sizes; (void)n_in; (void)out_size;

    prep_wh_kernel<<<TDIM, 256>>>(Wh);
    dim3 pg(NCH, BROWS / MTILE);   // (chunk, tile)
    prep_x_kernel<<<pg, 128>>>(x, Wb);
    surv_f16h_kernel<<<BROWS / MTILE, NTHREADS>>>(bh, bb, out);
}

// round 14
// speedup vs baseline: 1.3205x; 1.0517x over previous
#include <cuda_runtime.h>
#include <cuda_fp16.h>
#include <cstdint>

// out[b,t] = cumsum_t( relu(x @ Wh^T + bh) ) + (x @ Wb^T + bb)
//   x [16384,1024] f32, Wh [512,1024] f32, bh[512], Wb[1,1024], bb[1]
//
// fp16 mma.sync m16n8k16. Main kernel (R13, unchanged): CTA = 32 rows x 512
// cols, 256 threads, 2 CTAs/SM, warp-independent mainloop (per-warp cp.async
// A-rings + direct-LDG B, zero CTA barriers).
// R14: ONE merged prepass kernel: blocks 0..511 convert x tiles to fp16
// A-fragment order (smem-staged, coalesced) AND compute the exact fp32 base
// GEMV g_base; blocks 512..527 convert Wh to B-fragment order likewise.

#define DDIM   1024
#define TDIM   512
#define BROWS  16384
#define MTILE  32
#define NCH    32
#define NTHREADS 256

__device__ __half g_whs[TDIM * DDIM];   // B: [chunk][jg][lane][8 halfs]
__device__ __half g_xh[BROWS * DDIM];   // A: [tile][chunk][(i,G)][lane][8 halfs]
__device__ float  g_base[BROWS];        // x @ Wb (fp32, deterministic)

__device__ __forceinline__ void mma_f16(float* c, uint32_t a0, uint32_t a1,
                                        uint32_t a2, uint32_t a3,
                                        uint32_t b0, uint32_t b1) {
    asm volatile(
        "mma.sync.aligned.m16n8k16.row.col.f32.f16.f16.f32 "
        "{%0,%1,%2,%3}, {%4,%5,%6,%7}, {%8,%9}, {%0,%1,%2,%3};"
        : "+f"(c[0]), "+f"(c[1]), "+f"(c[2]), "+f"(c[3])
        : "r"(a0), "r"(a1), "r"(a2), "r"(a3), "r"(b0), "r"(b1));
}
__device__ __forceinline__ void cp16(void* dst_s, const void* src_g) {
    uint32_t d = (uint32_t)__cvta_generic_to_shared(dst_s);
    asm volatile("cp.async.cg.shared.global [%0], [%1], 16;" :: "r"(d), "l"(src_g));
}

// ---- merged prepass ----
// thread t handles row = t>>3 (0..31), q = t&7 (8-k group within a 64-k pair
// of chunks). Per-thread constants: cl = q>>2 (chunk parity),
// G = (q&3)>>1, u = (q&3)&1; per element e (0..8): lk = e>>1, w = e&1.
// smem staging gives fully coalesced 16B/thread global stores.
__global__ void __launch_bounds__(256) prep_all_kernel(const float* __restrict__ x,
                                                       const float* __restrict__ Wh,
                                                       const float* __restrict__ Wb) {
    __shared__ __half sbuf[2048];    // 2 chunks x 1024 halves
    const int b = blockIdx.x;
    const int t = threadIdx.x;
    const int q  = t & 7;
    const int cl = q >> 2;
    const int G  = (q & 3) >> 1;
    const int u  = (q & 3) & 1;
    __half* sb = sbuf + cl * 1024;

    if (b < 512) {
        // ---- x tile b: rows b*32 .. +31 ----
        const int row = t >> 3;
        const float* xrow = x + (size_t)(b * 32 + row) * DDIM + q * 8;
        const int ii = (row >> 4) & 1, rh = (row >> 3) & 1, l4r = row & 7;
        const int base = (ii * 2 + G) * 256 + 4 * l4r * 8 + 4 * u + 2 * rh;
        float bacc = 0.f;
        #pragma unroll 1
        for (int it = 0; it < 16; it++) {
            float4 v0 = *(const float4*)(xrow + it * 64);
            float4 v1 = *(const float4*)(xrow + it * 64 + 4);
            float4 w0 = *(const float4*)(Wb + it * 64 + q * 8);
            float4 w1 = *(const float4*)(Wb + it * 64 + q * 8 + 4);
            bacc = fmaf(v0.x, w0.x, bacc); bacc = fmaf(v0.y, w0.y, bacc);
            bacc = fmaf(v0.z, w0.z, bacc); bacc = fmaf(v0.w, w0.w, bacc);
            bacc = fmaf(v1.x, w1.x, bacc); bacc = fmaf(v1.y, w1.y, bacc);
            bacc = fmaf(v1.z, w1.z, bacc); bacc = fmaf(v1.w, w1.w, bacc);
            sb[base + 0]  = __float2half_rn(v0.x);
            sb[base + 1]  = __float2half_rn(v0.y);
            sb[base + 8]  = __float2half_rn(v0.z);
            sb[base + 9]  = __float2half_rn(v0.w);
            sb[base + 16] = __float2half_rn(v1.x);
            sb[base + 17] = __float2half_rn(v1.y);
            sb[base + 24] = __float2half_rn(v1.z);
            sb[base + 25] = __float2half_rn(v1.w);
            __syncthreads();
            *(uint4*)((char*)g_xh + (size_t)(b * 32 + 2 * it) * 2048 + t * 16) =
                *(const uint4*)((const char*)sbuf + t * 16);
            __syncthreads();
        }
        bacc += __shfl_down_sync(0xffffffffu, bacc, 4, 8);
        bacc += __shfl_down_sync(0xffffffffu, bacc, 2, 8);
        bacc += __shfl_down_sync(0xffffffffu, bacc, 1, 8);
        if (q == 0) g_base[b * 32 + row] = bacc;
    } else {
        // ---- Wh rows (b-512)*32 .. +31 ----
        const int rl = t >> 3;
        const int T  = (b - 512) * 32 + rl;
        const float* wrow = Wh + (size_t)T * DDIM + q * 8;
        const int l4 = T & 7, jg_l = rl >> 3;
        const int base = jg_l * 256 + 4 * l4 * 8 + 4 * G + 2 * u;
        const size_t jgb = (size_t)(b - 512) * 2048;   // jg0 * 512 bytes
        #pragma unroll 1
        for (int it = 0; it < 16; it++) {
            float4 v0 = *(const float4*)(wrow + it * 64);
            float4 v1 = *(const float4*)(wrow + it * 64 + 4);
            sb[base + 0]  = __float2half_rn(v0.x);
            sb[base + 1]  = __float2half_rn(v0.y);
            sb[base + 8]  = __float2half_rn(v0.z);
            sb[base + 9]  = __float2half_rn(v0.w);
            sb[base + 16] = __float2half_rn(v1.x);
            sb[base + 17] = __float2half_rn(v1.y);
            sb[base + 24] = __float2half_rn(v1.z);
            sb[base + 25] = __float2half_rn(v1.w);
            __syncthreads();
            *(uint4*)((char*)g_whs + (size_t)(2 * it + (t >> 7)) * 32768 + jgb +
                      (t & 127) * 16) =
                *(const uint4*)((const char*)sbuf + t * 16);
            __syncthreads();
        }
    }
}

__global__ void __launch_bounds__(NTHREADS, 2)
surv_f16i_kernel(const float* __restrict__ bh,
                 const float* __restrict__ bb,
                 float* __restrict__ out)
{
    __shared__ __align__(16) char As[8 * 4 * 2048];   // per-warp 4-stage A rings
    __shared__ float seg_s[MTILE * 8];

    const int tid  = threadIdx.x;
    const int nw   = tid >> 5;
    const int lane = tid & 31;
    const int l4   = lane >> 2;
    const int lk   = lane & 3;
    const int tile = blockIdx.x;
    const int row0 = tile * MTILE;

    const char* axsrc = (const char*)g_xh + (size_t)tile * 65536 + lane * 16;
    char* aring = As + nw * 8192 + lane * 16;
    const char* bgm = (const char*)g_whs + nw * 4096 + lane * 16;

    float acc[2][8][4];
    #pragma unroll
    for (int i = 0; i < 2; i++)
        #pragma unroll
        for (int j = 0; j < 8; j++)
            #pragma unroll
            for (int q = 0; q < 4; q++) acc[i][j][q] = 0.f;

    // prologue: A stages 0..2, B chunk 0
    #pragma unroll
    for (int s = 0; s < 3; s++) {
        const char* src = axsrc + (size_t)s * 2048;
        char* dst = aring + s * 2048;
        #pragma unroll
        for (int i = 0; i < 4; i++)
            cp16(dst + i * 512, src + i * 512);
        asm volatile("cp.async.commit_group;" ::: "memory");
    }
    uint4 LB[8];
    #pragma unroll
    for (int j = 0; j < 8; j++)
        LB[j] = *(const uint4*)(bgm + j * 512);

    // ---- mainloop: warp-independent, no CTA barriers ----
    #pragma unroll 1
    for (int c = 0; c < NCH; c++) {
        if (c <= NCH - 3)      asm volatile("cp.async.wait_group 2;" ::: "memory");
        else if (c == NCH - 2) asm volatile("cp.async.wait_group 1;" ::: "memory");
        else                   asm volatile("cp.async.wait_group 0;" ::: "memory");
        __syncwarp();

        const char* xaddr = aring + (c & 3) * 2048;
        uint4 LA00 = *(const uint4*)(xaddr);
        uint4 LA01 = *(const uint4*)(xaddr + 512);
        uint4 LA10 = *(const uint4*)(xaddr + 1024);
        uint4 LA11 = *(const uint4*)(xaddr + 1536);

        if (c + 3 < NCH) {   // refill ring stage (c+3)&3
            const char* src = axsrc + (size_t)(c + 3) * 2048;
            char* dst = aring + ((c + 3) & 3) * 2048;
            #pragma unroll
            for (int i = 0; i < 4; i++)
                cp16(dst + i * 512, src + i * 512);
            asm volatile("cp.async.commit_group;" ::: "memory");
        }

        const char* bnext = bgm + (size_t)((c + 1 < NCH) ? (c + 1) : c) * 32768;
        #pragma unroll
        for (int j = 0; j < 8; j++) {
            uint4 b = LB[j];
            mma_f16(acc[0][j], LA00.x, LA00.y, LA00.z, LA00.w, b.x, b.y);
            mma_f16(acc[1][j], LA10.x, LA10.y, LA10.z, LA10.w, b.x, b.y);
            mma_f16(acc[0][j], LA01.x, LA01.y, LA01.z, LA01.w, b.z, b.w);
            mma_f16(acc[1][j], LA11.x, LA11.y, LA11.z, LA11.w, b.z, b.w);
            LB[j] = *(const uint4*)(bnext + j * 512);
        }
    }

    // ---- per-row segmented scan over this warp's 64 cols ----
    float2 bhv[8];
    #pragma unroll
    for (int j = 0; j < 8; j++)
        bhv[j] = __ldg((const float2*)(bh + nw * 64 + 8 * j + 2 * lk));

    #pragma unroll
    for (int i = 0; i < 2; i++) {
        #pragma unroll
        for (int hh = 0; hh < 2; hh++) {
            const int r = 16 * i + 8 * hh + l4;
            float carry = 0.f;
            #pragma unroll
            for (int j = 0; j < 8; j++) {
                float v0 = fmaxf(acc[i][j][2 * hh]     + bhv[j].x, 0.f);
                float v1 = fmaxf(acc[i][j][2 * hh + 1] + bhv[j].y, 0.f);
                float p = v0 + v1;
                float incl = p, t;
                t = __shfl_up_sync(0xffffffffu, incl, 1, 4); if (lk >= 1) incl += t;
                t = __shfl_up_sync(0xffffffffu, incl, 2, 4); if (lk >= 2) incl += t;
                float excl = incl - p;
                acc[i][j][2 * hh]     = carry + excl + v0;
                acc[i][j][2 * hh + 1] = carry + incl;
                carry += __shfl_sync(0xffffffffu, incl, 3, 4);
            }
            if (lk == 0) seg_s[r * 8 + nw] = carry;
        }
    }
    __syncthreads();   // the ONE CTA barrier

    // ---- cross-warp segment prefix + base, store ----
    const float bbv = bb[0];
    #pragma unroll
    for (int i = 0; i < 2; i++) {
        #pragma unroll
        for (int hh = 0; hh < 2; hh++) {
            const int r = 16 * i + 8 * hh + l4;
            float g = __ldg(&g_base[row0 + r]) + bbv;
            #pragma unroll
            for (int s = 0; s < 8; s++)
                if (s < nw) g += seg_s[r * 8 + s];
            float* orow = out + (size_t)(row0 + r) * TDIM + nw * 64 + 2 * lk;
            #pragma unroll
            for (int j = 0; j < 8; j++) {
                float2 o;
                o.x = acc[i][j][2 * hh]     + g;
                o.y = acc[i][j][2 * hh + 1] + g;
                *(float2*)(orow + 8 * j) = o;
            }
        }
    }
}

extern "C" void kernel_launch(void* const* d_in, const int* in_sizes, int n_in,
                              void* d_out, int out_size)
{
    const float* x  = (const float*)d_in[0];
    const float* Wh = (const float*)d_in[1];
    const float* bh = (const float*)d_in[2];
    const float* Wb = (const float*)d_in[3];
    const float* bb = (const float*)d_in[4];
    float* out = (float*)d_out;
    (void)in_sizes; (void)n_in; (void)out_size;

    prep_all_kernel<<<528, 256>>>(x, Wh, Wb);
    surv_f16i_kernel<<<BROWS / MTILE, NTHREADS>>>(bh, bb, out);
}